// round 16
// baseline (speedup 1.0000x reference)
#include <cuda_runtime.h>
#include <cuda_fp16.h>
#include <cstdint>
#include <math.h>

// Problem constants
#define BB   2
#define SS   2048
#define DD   1024
#define HH   16
#define DHH  64
#define MTOT (BB * SS)   // 4096

// ---------------------------------------------------------------------------
// Scratch (__device__ globals; allocation-free rule)
// ---------------------------------------------------------------------------
__device__ __half g_x[(size_t)MTOT * DD];         // activation fp16
__device__ __half g_w[4 * (size_t)DD * DD];       // weights fp16 (q,k,v,o)
__device__ __half g_q[(size_t)MTOT * DD];         // [B,H,S,64] q (log2e-scaled)
__device__ __half g_k[(size_t)MTOT * DD];         // k
__device__ __half g_v[(size_t)MTOT * DD];         // v
__device__ __half g_c[(size_t)MTOT * DD];         // ctx fp16
__device__ unsigned int g_mbits[(size_t)BB * SS * SS / 32];  // mask bitmap

// ---------------------------------------------------------------------------
// PTX helpers
// ---------------------------------------------------------------------------
__device__ __forceinline__ uint32_t smem_u32(const void* p) {
    uint32_t a;
    asm("{ .reg .u64 t; cvta.to.shared.u64 t, %1; cvt.u32.u64 %0, t; }"
        : "=r"(a) : "l"(p));
    return a;
}
#define CP_ASYNC16(dst, src) \
    asm volatile("cp.async.cg.shared.global [%0], [%1], 16;" :: "r"(dst), "l"(src))
#define CP_COMMIT() asm volatile("cp.async.commit_group;" ::: "memory")
#define CP_WAIT(n)  asm volatile("cp.async.wait_group %0;" :: "n"(n) : "memory")

__device__ __forceinline__ void ldm_x4(uint32_t* r, uint32_t addr) {
    asm volatile("ldmatrix.sync.aligned.m8n8.x4.shared.b16 {%0,%1,%2,%3}, [%4];"
        : "=r"(r[0]), "=r"(r[1]), "=r"(r[2]), "=r"(r[3]) : "r"(addr));
}
__device__ __forceinline__ void ldm_x4t(uint32_t* r, uint32_t addr) {
    asm volatile("ldmatrix.sync.aligned.m8n8.x4.trans.shared.b16 {%0,%1,%2,%3}, [%4];"
        : "=r"(r[0]), "=r"(r[1]), "=r"(r[2]), "=r"(r[3]) : "r"(addr));
}
// D += A*B  (m16n8k16, fp16 in, fp32 accum)
__device__ __forceinline__ void mma16816(float* c, const uint32_t* a,
                                         const uint32_t* b) {
    asm volatile(
        "mma.sync.aligned.m16n8k16.row.col.f32.f16.f16.f32 "
        "{%0,%1,%2,%3}, {%4,%5,%6,%7}, {%8,%9}, {%0,%1,%2,%3};"
        : "+f"(c[0]), "+f"(c[1]), "+f"(c[2]), "+f"(c[3])
        : "r"(a[0]), "r"(a[1]), "r"(a[2]), "r"(a[3]), "r"(b[0]), "r"(b[1]));
}
__device__ __forceinline__ uint32_t bc32(__half2 v) {
    return *reinterpret_cast<uint32_t*>(&v);
}

// ---------------------------------------------------------------------------
// Fused prep: 4 weight cvts + query cvt + mask bit-pack in ONE launch.
// Flat index ranges:  [0, 2^20)           weights (z = i>>18)
//                     [2^20, 2^21)        query float4s
//                     [2^21, 2^21+2^18)   mask words
// ---------------------------------------------------------------------------
#define PREP_W   1048576
#define PREP_X   1048576
#define PREP_M   262144
#define PREP_TOT (PREP_W + PREP_X + PREP_M)   // 2359296

__global__ __launch_bounds__(256) void prep_kernel(
    const float* __restrict__ w0, const float* __restrict__ w1,
    const float* __restrict__ w2, const float* __restrict__ w3,
    const float* __restrict__ query, const int* __restrict__ mask,
    __half* __restrict__ wout, __half* __restrict__ xout,
    unsigned int* __restrict__ bits)
{
    const int i = blockIdx.x * 256 + threadIdx.x;
    if (i < PREP_W) {
        const int z = i >> 18, j = i & 0x3FFFF;
        const float* src = (z == 0) ? w0 : (z == 1) ? w1 : (z == 2) ? w2 : w3;
        float4 v = ((const float4*)src)[j];
        __half2* op = (__half2*)(wout + (size_t)z * DD * DD + (size_t)j * 4);
        op[0] = __floats2half2_rn(v.x, v.y);
        op[1] = __floats2half2_rn(v.z, v.w);
    } else if (i < PREP_W + PREP_X) {
        const int j = i - PREP_W;
        float4 v = ((const float4*)query)[j];
        __half2* op = (__half2*)(xout + (size_t)j * 4);
        op[0] = __floats2half2_rn(v.x, v.y);
        op[1] = __floats2half2_rn(v.z, v.w);
    } else if (i < PREP_TOT) {
        const int j = i - PREP_W - PREP_X;
        const int4* p = (const int4*)(mask + (size_t)j * 32);
        unsigned int w = 0;
#pragma unroll
        for (int k = 0; k < 8; k++) {
            int4 v = p[k];
            w |= (v.x ? 1u : 0u) << (k * 4 + 0);
            w |= (v.y ? 1u : 0u) << (k * 4 + 1);
            w |= (v.z ? 1u : 0u) << (k * 4 + 2);
            w |= (v.w ? 1u : 0u) << (k * 4 + 3);
        }
        bits[j] = w;
    }
}

// ---------------------------------------------------------------------------
// GEMM mainloop: fp16 1-pass, CTA 128x128, 128 threads (4 warps, each 64x64),
// BK=64, 2-stage ring, 2 CTAs/SM. MMA:ldmatrix ratio 4:1 -> smem-balanced.
// ---------------------------------------------------------------------------
#define GROWB    144
#define GOFF_A   0
#define GOFF_W   (128 * GROWB)            // 18432
#define GSTAGE_B (256 * GROWB)            // 36864 (A 128 rows + W 128 rows)
#define SMEM_GG  (2 * GSTAGE_B)           // 73728

struct GemmAcc { float c[4][8][4]; };

__device__ __forceinline__ void gemm_mainloop(
    const __half* A, const __half* W,
    int row0, int col0, uint32_t sb, GemmAcc& acc)
{
    const int tid  = threadIdx.x;
    const int lane = tid & 31;
    const int w    = tid >> 5;     // 0..3
    const int wm   = w & 1;        // 64-row half
    const int wn   = w >> 1;       // 64-col half

#pragma unroll
    for (int i = 0; i < 4; i++)
#pragma unroll
        for (int j = 0; j < 8; j++)
#pragma unroll
            for (int e = 0; e < 4; e++) acc.c[i][j][e] = 0.f;

    const uint32_t aoff = (uint32_t)((lane & 15) * GROWB + ((lane >> 4) & 1) * 16);
    const uint32_t boff = (uint32_t)(((((lane >> 4) & 1) * 8) + (lane & 7)) * GROWB
                                     + ((lane >> 3) & 1) * 16);

    auto issue = [&](int cidx) {
        const uint32_t bb = sb + (uint32_t)(cidx & 1) * GSTAGE_B;
        const int kc = cidx * 64;
#pragma unroll
        for (int i = 0; i < 8; i++) {       // A: 128 rows
            const int u = tid + i * 128;
            const int row = u >> 3, sg = u & 7;
            const uint32_t so = (uint32_t)(row * GROWB + sg * 16);
            CP_ASYNC16(bb + GOFF_A + so, A + (size_t)(row0 + row) * DD + kc + sg * 8);
        }
#pragma unroll
        for (int i = 0; i < 8; i++) {       // W: 128 rows
            const int u = tid + i * 128;
            const int row = u >> 3, sg = u & 7;
            const uint32_t so = (uint32_t)(row * GROWB + sg * 16);
            CP_ASYNC16(bb + GOFF_W + so, W + (size_t)(col0 + row) * DD + kc + sg * 8);
        }
    };

    const int NCH = DD / 64;   // 16
    issue(0); CP_COMMIT();
    issue(1); CP_COMMIT();

    for (int cidx = 0; cidx < NCH; cidx++) {
        CP_WAIT(1);
        __syncthreads();

        const uint32_t bb = sb + (uint32_t)(cidx & 1) * GSTAGE_B;
#pragma unroll
        for (int ks = 0; ks < 4; ks++) {
            const uint32_t k0b = (uint32_t)(ks * 32);
            uint32_t aa[4][4];
#pragma unroll
            for (int i = 0; i < 4; i++) {
                const uint32_t ao = (uint32_t)((wm * 64 + i * 16) * GROWB)
                                  + aoff + k0b;
                ldm_x4(aa[i], bb + GOFF_A + ao);
            }
#pragma unroll
            for (int jp = 0; jp < 4; jp++) {
                uint32_t tw[4];
                const uint32_t bo = (uint32_t)((wn * 64 + jp * 16) * GROWB)
                                  + boff + k0b;
                ldm_x4(tw, bb + GOFF_W + bo);
#pragma unroll
                for (int i = 0; i < 4; i++) {
                    mma16816(acc.c[i][jp*2],   aa[i], tw);
                    mma16816(acc.c[i][jp*2+1], aa[i], tw + 2);
                }
            }
        }
        __syncthreads();                    // stage free before overwrite
        if (cidx + 2 < NCH) issue(cidx + 2);
        CP_COMMIT();
    }
}

// ---- final GEMM: fp32 out = acc + bias (Wo path)
__global__ __launch_bounds__(128, 2)
void gemm_out_kernel(const __half* __restrict__ A,
                     const __half* __restrict__ W,
                     const float* __restrict__ bias,
                     float* __restrict__ out)
{
    extern __shared__ char smem[];
    const uint32_t sb = smem_u32(smem);
    const int lane = threadIdx.x & 31;
    const int w    = threadIdx.x >> 5;
    const int wm = w & 1, wn = w >> 1;
    const int row0 = blockIdx.y * 128, col0 = blockIdx.x * 128;

    GemmAcc acc;
    gemm_mainloop(A, W, row0, col0, sb, acc);

    const int g = lane >> 2, tq = lane & 3;
#pragma unroll
    for (int i = 0; i < 4; i++) {
        const int mrow = row0 + wm * 64 + i * 16 + g;
#pragma unroll
        for (int j = 0; j < 8; j++) {
            const int col = col0 + wn * 64 + j * 8 + tq * 2;
            const float b0 = bias[col], b1 = bias[col + 1];
            *(float2*)(out + (size_t)mrow * DD + col) =
                make_float2(acc.c[i][j][0] + b0, acc.c[i][j][1] + b1);
            *(float2*)(out + (size_t)(mrow + 8) * DD + col) =
                make_float2(acc.c[i][j][2] + b0, acc.c[i][j][3] + b1);
        }
    }
}

// ---- QKV GEMM: z=0 -> q (log2e-scaled), z=1 -> k, z=2 -> v; [B,H,S,64]
__global__ __launch_bounds__(128, 2)
void gemm_qkv_kernel(const __half* __restrict__ A,
                     const __half* __restrict__ WALL,
                     const float* __restrict__ bq, const float* __restrict__ bk,
                     const float* __restrict__ bv,
                     __half* __restrict__ qq,
                     __half* __restrict__ kk, __half* __restrict__ vv)
{
    extern __shared__ char smem[];
    const uint32_t sb = smem_u32(smem);
    const int z = blockIdx.z;
    const __half* W = WALL + (size_t)z * DD * DD;
    const float* bias = (z == 0) ? bq : (z == 1) ? bk : bv;
    const float alpha = (z == 0) ? 0.125f * 1.44269504f : 1.0f;
    __half* O = (z == 0) ? qq : (z == 1) ? kk : vv;

    const int lane = threadIdx.x & 31;
    const int w    = threadIdx.x >> 5;
    const int wm = w & 1, wn = w >> 1;
    const int row0 = blockIdx.y * 128, col0 = blockIdx.x * 128;

    GemmAcc acc;
    gemm_mainloop(A, W, row0, col0, sb, acc);

    const int g = lane >> 2, tq = lane & 3;
#pragma unroll
    for (int i = 0; i < 4; i++) {
        const int m0r = row0 + wm * 64 + i * 16 + g;
#pragma unroll
        for (int j = 0; j < 8; j++) {
            const int col = col0 + wn * 64 + j * 8 + tq * 2;
            const float b0 = bias[col], b1 = bias[col + 1];
            const int h = col >> 6, d = col & 63;
#pragma unroll
            for (int half = 0; half < 2; half++) {
                const int m = m0r + half * 8;
                const int b = m >> 11, s = m & 2047;
                const float v0 = (acc.c[i][j][half * 2 + 0] + b0) * alpha;
                const float v1 = (acc.c[i][j][half * 2 + 1] + b1) * alpha;
                const size_t o = (((size_t)(b * HH + h) * SS + s) << 6) + d;
                *(__half2*)(O + o) = __floats2half2_rn(v0, v1);
            }
        }
    }
}

// ---------------------------------------------------------------------------
// Flash attention, fp16 1-pass, m32 warps, max-free softmax (log2 domain,
// S init -8). Masking post-exp2 via packed bitmask. 2 CTAs/SM; 4-stage ring.
// ---------------------------------------------------------------------------
#define DPADB    144
#define AQROWS   128
#define QTILE_B  (AQROWS * DPADB)       // 18432
#define KVT_B    (64 * DPADB)           // 9216
#define AOFF_Q   0
#define AOFF_ST  QTILE_B
#define STAGE_B  (2 * KVT_B)            // 18432
#define AOFF_KH  0
#define AOFF_VH  (1 * KVT_B)
#define SMEM_ATT (QTILE_B + 4 * STAGE_B)   // 92160

__global__ __launch_bounds__(128, 2)
void attn_mma_kernel(const __half* __restrict__ Q,
                     const __half* __restrict__ K,
                     const __half* __restrict__ V,
                     const unsigned long long* __restrict__ mbits,
                     __half* __restrict__ C)
{
    extern __shared__ char smem[];
    const uint32_t sb = smem_u32(smem);
    const int tid = threadIdx.x, lane = tid & 31, w = tid >> 5;   // w: 0..3
    const int bh = blockIdx.y, b = bh >> 4, h = bh & 15;
    const int q0 = blockIdx.x * AQROWS;
    const size_t hoff = (size_t)bh * SS * 64;

    auto issue_kv = [&](int kt) {
        const uint32_t st = sb + AOFF_ST + (uint32_t)(kt & 3) * STAGE_B;
#pragma unroll
        for (int u = tid; u < 512; u += 128) {
            const int r = u >> 3, sg = u & 7;
            const uint32_t so = (uint32_t)(r * DPADB + sg * 16);
            const size_t go = hoff + (size_t)(kt * 64 + r) * 64 + sg * 8;
            CP_ASYNC16(st + AOFF_KH + so, K + go);
            CP_ASYNC16(st + AOFF_VH + so, V + go);
        }
    };

    for (int u = tid; u < 1024; u += 128) {
        const int r = u >> 3, sg = u & 7;
        const uint32_t so = (uint32_t)(r * DPADB + sg * 16);
        const size_t go = hoff + (size_t)(q0 + r) * 64 + sg * 8;
        CP_ASYNC16(sb + AOFF_Q + so, Q + go);
    }
    issue_kv(0); CP_COMMIT();
    issue_kv(1); CP_COMMIT();
    issue_kv(2); CP_COMMIT();
    CP_WAIT(2); __syncthreads();   // Q + stage 0 ready

    // Q fragments: 2 row-blocks x 4 k-chunks
    uint32_t qf[2][4][4];
#pragma unroll
    for (int rb = 0; rb < 2; rb++) {
        const uint32_t ao = (uint32_t)((w * 32 + rb * 16 + (lane & 15)) * DPADB
                                       + ((lane >> 4) & 1) * 16);
#pragma unroll
        for (int c = 0; c < 4; c++)
            ldm_x4(qf[rb][c], sb + AOFF_Q + ao + c * 32);
    }

    const uint32_t koff = (uint32_t)(((((lane >> 4) & 1) * 8) + (lane & 7)) * DPADB
                                     + ((lane >> 3) & 1) * 16);
    const uint32_t voff = (uint32_t)((lane & 15) * DPADB + ((lane >> 4) & 1) * 16);

    float O[2][8][4];
#pragma unroll
    for (int rb = 0; rb < 2; rb++)
#pragma unroll
        for (int j = 0; j < 8; j++)
#pragma unroll
            for (int e = 0; e < 4; e++) O[rb][j][e] = 0.f;
    float l[4] = { 0.f, 0.f, 0.f, 0.f };

    const int g = lane >> 2;
    const int tq2 = (lane & 3) * 2;
    const unsigned long long* bp =
        mbits + ((size_t)(b * SS) + q0 + w * 32 + g) * 32;

    for (int kt = 0; kt < 32; kt++) {
        CP_WAIT(1);
        __syncthreads();

        // mask bits (latency hidden by QK MMAs below)
        unsigned long long B0 = bp[kt];
        unsigned long long B1 = bp[kt + 256];
        unsigned long long B2 = bp[kt + 512];
        unsigned long long B3 = bp[kt + 768];

        // ---- QK: S = Q.K - 8 (log2 domain, static shift via C-init)
        const uint32_t st = sb + AOFF_ST + (uint32_t)(kt & 3) * STAGE_B;
        float S[2][8][4];
#pragma unroll
        for (int rb = 0; rb < 2; rb++)
#pragma unroll
            for (int j = 0; j < 8; j++)
#pragma unroll
                for (int e = 0; e < 4; e++) S[rb][j][e] = -8.f;
#pragma unroll
        for (int c = 0; c < 4; c++)
#pragma unroll
            for (int jp = 0; jp < 4; jp++) {
                uint32_t tk[4];
                const uint32_t ko = (uint32_t)(jp * 16 * DPADB) + koff + c * 32;
                ldm_x4(tk, st + AOFF_KH + ko);
                mma16816(S[0][jp*2],   qf[0][c], tk);
                mma16816(S[0][jp*2+1], qf[0][c], tk + 2);
                mma16816(S[1][jp*2],   qf[1][c], tk);
                mma16816(S[1][jp*2+1], qf[1][c], tk + 2);
            }

        // ---- exp2 (no max pass) + bitmask zeroing + pack P
        uint32_t PH[2][8][2];
#pragma unroll
        for (int j = 0; j < 8; j++) {
            const int sh = j * 8 + tq2;
            const uint32_t b0 = (uint32_t)(B0 >> sh);
            const uint32_t b1 = (uint32_t)(B1 >> sh);
            const uint32_t b2 = (uint32_t)(B2 >> sh);
            const uint32_t b3 = (uint32_t)(B3 >> sh);
            float p00 = exp2f(S[0][j][0]);
            float p01 = exp2f(S[0][j][1]);
            float p02 = exp2f(S[0][j][2]);
            float p03 = exp2f(S[0][j][3]);
            float p10 = exp2f(S[1][j][0]);
            float p11 = exp2f(S[1][j][1]);
            float p12 = exp2f(S[1][j][2]);
            float p13 = exp2f(S[1][j][3]);
            p00 = (b0 & 1u) ? 0.f : p00;  p01 = (b0 & 2u) ? 0.f : p01;
            p02 = (b1 & 1u) ? 0.f : p02;  p03 = (b1 & 2u) ? 0.f : p03;
            p10 = (b2 & 1u) ? 0.f : p10;  p11 = (b2 & 2u) ? 0.f : p11;
            p12 = (b3 & 1u) ? 0.f : p12;  p13 = (b3 & 2u) ? 0.f : p13;
            l[0] += p00 + p01; l[1] += p02 + p03;
            l[2] += p10 + p11; l[3] += p12 + p13;
            PH[0][j][0] = bc32(__floats2half2_rn(p00, p01));
            PH[0][j][1] = bc32(__floats2half2_rn(p02, p03));
            PH[1][j][0] = bc32(__floats2half2_rn(p10, p11));
            PH[1][j][1] = bc32(__floats2half2_rn(p12, p13));
        }

        // ---- PV: O += P . V; V frags shared across row-blocks
#pragma unroll
        for (int t = 0; t < 4; t++) {
            uint32_t a0[4] = { PH[0][2*t][0], PH[0][2*t][1],
                               PH[0][2*t+1][0], PH[0][2*t+1][1] };
            uint32_t a1[4] = { PH[1][2*t][0], PH[1][2*t][1],
                               PH[1][2*t+1][0], PH[1][2*t+1][1] };
#pragma unroll
            for (int jp = 0; jp < 4; jp++) {
                uint32_t tv[4];
                const uint32_t vo = (uint32_t)(t * 16 * DPADB) + voff + jp * 32;
                ldm_x4t(tv, st + AOFF_VH + vo);
                mma16816(O[0][jp*2],   a0, tv);
                mma16816(O[0][jp*2+1], a0, tv + 2);
                mma16816(O[1][jp*2],   a1, tv);
                mma16816(O[1][jp*2+1], a1, tv + 2);
            }
        }

        if (kt + 3 < 32) issue_kv(kt + 3);
        CP_COMMIT();
    }

    // ---- epilogue: 4 rows per thread, single l reduce
#pragma unroll
    for (int rr = 0; rr < 4; rr++) {
        l[rr] += __shfl_xor_sync(0xFFFFFFFFu, l[rr], 1);
        l[rr] += __shfl_xor_sync(0xFFFFFFFFu, l[rr], 2);
    }
    const int colb = h * 64 + tq2;
#pragma unroll
    for (int rr = 0; rr < 4; rr++) {
        const int rb = rr >> 1, hh = rr & 1;
        const float inv = 1.f / l[rr];
        const size_t r = (size_t)(b * SS) + q0 + w * 32 + g + rr * 8;
#pragma unroll
        for (int j = 0; j < 8; j++) {
            *(__half2*)(C + r * DD + colb + j * 8) =
                __floats2half2_rn(O[rb][j][hh*2] * inv, O[rb][j][hh*2+1] * inv);
        }
    }
}

// ---------------------------------------------------------------------------
// Launch
// ---------------------------------------------------------------------------
extern "C" void kernel_launch(void* const* d_in, const int* in_sizes, int n_in,
                              void* d_out, int out_size)
{
    const float* query = (const float*)d_in[0];
    const int*   mask  = (const int*)d_in[1];
    const float* Wq = (const float*)d_in[2];
    const float* bq = (const float*)d_in[3];
    const float* Wk = (const float*)d_in[4];
    const float* bk = (const float*)d_in[5];
    const float* Wv = (const float*)d_in[6];
    const float* bv = (const float*)d_in[7];
    const float* Wo = (const float*)d_in[8];
    const float* bo = (const float*)d_in[9];
    float* out = (float*)d_out;

    __half *xx, *wp, *qq, *kk, *vv, *cc;
    unsigned int* mb;
    cudaGetSymbolAddress((void**)&xx, g_x);
    cudaGetSymbolAddress((void**)&wp, g_w);
    cudaGetSymbolAddress((void**)&qq, g_q);
    cudaGetSymbolAddress((void**)&kk, g_k);
    cudaGetSymbolAddress((void**)&vv, g_v);
    cudaGetSymbolAddress((void**)&cc, g_c);
    cudaGetSymbolAddress((void**)&mb, g_mbits);

    cudaFuncSetAttribute(gemm_qkv_kernel,
                         cudaFuncAttributeMaxDynamicSharedMemorySize, SMEM_GG);
    cudaFuncSetAttribute(gemm_out_kernel,
                         cudaFuncAttributeMaxDynamicSharedMemorySize, SMEM_GG);
    cudaFuncSetAttribute(attn_mma_kernel,
                         cudaFuncAttributeMaxDynamicSharedMemorySize, SMEM_ATT);

    prep_kernel<<<PREP_TOT / 256, 256>>>(Wq, Wk, Wv, Wo, query, mask,
                                         wp, xx, mb);

    dim3 qkvG(DD / 128, MTOT / 128, 3);     // (8, 32, 3) = 768 CTAs
    gemm_qkv_kernel<<<qkvG, 128, SMEM_GG>>>(xx, wp, bq, bk, bv, qq, kk, vv);

    dim3 aG(SS / AQROWS, BB * HH);          // (16, 32) = 512 CTAs
    attn_mma_kernel<<<aG, 128, SMEM_ATT>>>(
        qq, kk, vv, (const unsigned long long*)mb, cc);

    dim3 oG(DD / 128, MTOT / 128);          // (8, 32)
    gemm_out_kernel<<<oG, 128, SMEM_GG>>>(cc, wp + 3 * (size_t)DD * DD, bo, out);
}

// round 17
// speedup vs baseline: 1.0417x; 1.0417x over previous
#include <cuda_runtime.h>
#include <cuda_fp16.h>
#include <cstdint>
#include <math.h>

// Problem constants
#define BB   2
#define SS   2048
#define DD   1024
#define HH   16
#define DHH  64
#define MTOT (BB * SS)   // 4096

// ---------------------------------------------------------------------------
// Scratch (__device__ globals; allocation-free rule)
// ---------------------------------------------------------------------------
__device__ __half g_x[(size_t)MTOT * DD];         // activation fp16
__device__ __half g_w[4 * (size_t)DD * DD];       // weights fp16 (q,k,v,o)
__device__ __half g_q[(size_t)MTOT * DD];         // [B,H,S,64] q (log2e-scaled)
__device__ __half g_k[(size_t)MTOT * DD];         // k
__device__ __half g_v[(size_t)MTOT * DD];         // v
__device__ __half g_c[(size_t)MTOT * DD];         // ctx fp16
__device__ unsigned int g_mbits[(size_t)BB * SS * SS / 32];  // mask bitmap

// ---------------------------------------------------------------------------
// PTX helpers
// ---------------------------------------------------------------------------
__device__ __forceinline__ uint32_t smem_u32(const void* p) {
    uint32_t a;
    asm("{ .reg .u64 t; cvta.to.shared.u64 t, %1; cvt.u32.u64 %0, t; }"
        : "=r"(a) : "l"(p));
    return a;
}
#define CP_ASYNC16(dst, src) \
    asm volatile("cp.async.cg.shared.global [%0], [%1], 16;" :: "r"(dst), "l"(src))
#define CP_COMMIT() asm volatile("cp.async.commit_group;" ::: "memory")
#define CP_WAIT(n)  asm volatile("cp.async.wait_group %0;" :: "n"(n) : "memory")

__device__ __forceinline__ void ldm_x4(uint32_t* r, uint32_t addr) {
    asm volatile("ldmatrix.sync.aligned.m8n8.x4.shared.b16 {%0,%1,%2,%3}, [%4];"
        : "=r"(r[0]), "=r"(r[1]), "=r"(r[2]), "=r"(r[3]) : "r"(addr));
}
__device__ __forceinline__ void ldm_x4t(uint32_t* r, uint32_t addr) {
    asm volatile("ldmatrix.sync.aligned.m8n8.x4.trans.shared.b16 {%0,%1,%2,%3}, [%4];"
        : "=r"(r[0]), "=r"(r[1]), "=r"(r[2]), "=r"(r[3]) : "r"(addr));
}
// D += A*B  (m16n8k16, fp16 in, fp32 accum)
__device__ __forceinline__ void mma16816(float* c, const uint32_t* a,
                                         const uint32_t* b) {
    asm volatile(
        "mma.sync.aligned.m16n8k16.row.col.f32.f16.f16.f32 "
        "{%0,%1,%2,%3}, {%4,%5,%6,%7}, {%8,%9}, {%0,%1,%2,%3};"
        : "+f"(c[0]), "+f"(c[1]), "+f"(c[2]), "+f"(c[3])
        : "r"(a[0]), "r"(a[1]), "r"(a[2]), "r"(a[3]), "r"(b[0]), "r"(b[1]));
}
__device__ __forceinline__ uint32_t bc32(__half2 v) {
    return *reinterpret_cast<uint32_t*>(&v);
}

// ---------------------------------------------------------------------------
// Fused prep: 4 weight cvts + query cvt + mask bit-pack in ONE launch.
// ---------------------------------------------------------------------------
#define PREP_W   1048576
#define PREP_X   1048576
#define PREP_M   262144
#define PREP_TOT (PREP_W + PREP_X + PREP_M)   // 2359296

__global__ __launch_bounds__(256) void prep_kernel(
    const float* __restrict__ w0, const float* __restrict__ w1,
    const float* __restrict__ w2, const float* __restrict__ w3,
    const float* __restrict__ query, const int* __restrict__ mask,
    __half* __restrict__ wout, __half* __restrict__ xout,
    unsigned int* __restrict__ bits)
{
    const int i = blockIdx.x * 256 + threadIdx.x;
    if (i < PREP_W) {
        const int z = i >> 18, j = i & 0x3FFFF;
        const float* src = (z == 0) ? w0 : (z == 1) ? w1 : (z == 2) ? w2 : w3;
        float4 v = ((const float4*)src)[j];
        __half2* op = (__half2*)(wout + (size_t)z * DD * DD + (size_t)j * 4);
        op[0] = __floats2half2_rn(v.x, v.y);
        op[1] = __floats2half2_rn(v.z, v.w);
    } else if (i < PREP_W + PREP_X) {
        const int j = i - PREP_W;
        float4 v = ((const float4*)query)[j];
        __half2* op = (__half2*)(xout + (size_t)j * 4);
        op[0] = __floats2half2_rn(v.x, v.y);
        op[1] = __floats2half2_rn(v.z, v.w);
    } else if (i < PREP_TOT) {
        const int j = i - PREP_W - PREP_X;
        const int4* p = (const int4*)(mask + (size_t)j * 32);
        unsigned int w = 0;
#pragma unroll
        for (int k = 0; k < 8; k++) {
            int4 v = p[k];
            w |= (v.x ? 1u : 0u) << (k * 4 + 0);
            w |= (v.y ? 1u : 0u) << (k * 4 + 1);
            w |= (v.z ? 1u : 0u) << (k * 4 + 2);
            w |= (v.w ? 1u : 0u) << (k * 4 + 3);
        }
        bits[j] = w;
    }
}

// ---------------------------------------------------------------------------
// GEMM mainloop: fp16 1-pass, CTA 128x64 tile, 128 threads (4 warps 64x32),
// BK=64, 3-stage ring, 2 CTAs/SM (R15 proven config).
// ---------------------------------------------------------------------------
#define GROWB    144
#define GOFF_A   0
#define GOFF_W   (128 * GROWB)            // 18432
#define GSTAGE_B (192 * GROWB)            // 27648 (A 128 rows + W 64 rows)
#define SMEM_GG  (3 * GSTAGE_B)           // 82944

struct GemmAcc { float c[4][4][4]; };

__device__ __forceinline__ void gemm_mainloop(
    const __half* A, const __half* W,
    int row0, int col0, uint32_t sb, GemmAcc& acc)
{
    const int tid  = threadIdx.x;
    const int lane = tid & 31;
    const int w    = tid >> 5;     // 0..3
    const int wm   = w & 1;        // 64-row half
    const int wn   = w >> 1;       // 32-col half

#pragma unroll
    for (int i = 0; i < 4; i++)
#pragma unroll
        for (int j = 0; j < 4; j++)
#pragma unroll
            for (int e = 0; e < 4; e++) acc.c[i][j][e] = 0.f;

    const uint32_t aoff = (uint32_t)((lane & 15) * GROWB + ((lane >> 4) & 1) * 16);
    const uint32_t boff = (uint32_t)(((((lane >> 4) & 1) * 8) + (lane & 7)) * GROWB
                                     + ((lane >> 3) & 1) * 16);

    auto issue = [&](int cidx) {
        const uint32_t bb = sb + (uint32_t)(cidx % 3) * GSTAGE_B;
        const int kc = cidx * 64;
#pragma unroll
        for (int i = 0; i < 8; i++) {       // A: 128 rows
            const int u = tid + i * 128;
            const int row = u >> 3, sg = u & 7;
            const uint32_t so = (uint32_t)(row * GROWB + sg * 16);
            CP_ASYNC16(bb + GOFF_A + so, A + (size_t)(row0 + row) * DD + kc + sg * 8);
        }
#pragma unroll
        for (int i = 0; i < 4; i++) {       // W: 64 rows
            const int u = tid + i * 128;
            const int row = u >> 3, sg = u & 7;
            const uint32_t so = (uint32_t)(row * GROWB + sg * 16);
            CP_ASYNC16(bb + GOFF_W + so, W + (size_t)(col0 + row) * DD + kc + sg * 8);
        }
    };

    const int NCH = DD / 64;   // 16
    issue(0); CP_COMMIT();
    issue(1); CP_COMMIT();

    for (int cidx = 0; cidx < NCH; cidx++) {
        CP_WAIT(1);
        __syncthreads();

        const uint32_t bb = sb + (uint32_t)(cidx % 3) * GSTAGE_B;
#pragma unroll
        for (int ks = 0; ks < 4; ks++) {
            const uint32_t k0b = (uint32_t)(ks * 32);
            uint32_t aa[4][4], bw[4][2];
#pragma unroll
            for (int i = 0; i < 4; i++) {
                const uint32_t ao = (uint32_t)((wm * 64 + i * 16) * GROWB)
                                  + aoff + k0b;
                ldm_x4(aa[i], bb + GOFF_A + ao);
            }
#pragma unroll
            for (int jp = 0; jp < 2; jp++) {
                const uint32_t bo = (uint32_t)((wn * 32 + jp * 16) * GROWB)
                                  + boff + k0b;
                uint32_t tw[4];
                ldm_x4(tw, bb + GOFF_W + bo);
                bw[jp*2][0] = tw[0]; bw[jp*2][1] = tw[1];
                bw[jp*2+1][0] = tw[2]; bw[jp*2+1][1] = tw[3];
            }
#pragma unroll
            for (int i = 0; i < 4; i++)
#pragma unroll
                for (int j = 0; j < 4; j++)
                    mma16816(acc.c[i][j], aa[i], bw[j]);
        }
        if (cidx + 2 < NCH) issue(cidx + 2);
        CP_COMMIT();
    }
}

// ---- final GEMM: fp32 out = acc + bias (Wo path)
__global__ __launch_bounds__(128, 2)
void gemm_out_kernel(const __half* __restrict__ A,
                     const __half* __restrict__ W,
                     const float* __restrict__ bias,
                     float* __restrict__ out)
{
    extern __shared__ char smem[];
    const uint32_t sb = smem_u32(smem);
    const int lane = threadIdx.x & 31;
    const int w    = threadIdx.x >> 5;
    const int wm = w & 1, wn = w >> 1;
    const int row0 = blockIdx.y * 128, col0 = blockIdx.x * 64;

    GemmAcc acc;
    gemm_mainloop(A, W, row0, col0, sb, acc);

    const int g = lane >> 2, tq = lane & 3;
#pragma unroll
    for (int i = 0; i < 4; i++) {
        const int mrow = row0 + wm * 64 + i * 16 + g;
#pragma unroll
        for (int j = 0; j < 4; j++) {
            const int col = col0 + wn * 32 + j * 8 + tq * 2;
            const float b0 = bias[col], b1 = bias[col + 1];
            *(float2*)(out + (size_t)mrow * DD + col) =
                make_float2(acc.c[i][j][0] + b0, acc.c[i][j][1] + b1);
            *(float2*)(out + (size_t)(mrow + 8) * DD + col) =
                make_float2(acc.c[i][j][2] + b0, acc.c[i][j][3] + b1);
        }
    }
}

// ---- QKV GEMM: z=0 -> q (log2e-scaled), z=1 -> k, z=2 -> v; [B,H,S,64]
__global__ __launch_bounds__(128, 2)
void gemm_qkv_kernel(const __half* __restrict__ A,
                     const __half* __restrict__ WALL,
                     const float* __restrict__ bq, const float* __restrict__ bk,
                     const float* __restrict__ bv,
                     __half* __restrict__ qq,
                     __half* __restrict__ kk, __half* __restrict__ vv)
{
    extern __shared__ char smem[];
    const uint32_t sb = smem_u32(smem);
    const int z = blockIdx.z;
    const __half* W = WALL + (size_t)z * DD * DD;
    const float* bias = (z == 0) ? bq : (z == 1) ? bk : bv;
    const float alpha = (z == 0) ? 0.125f * 1.44269504f : 1.0f;
    __half* O = (z == 0) ? qq : (z == 1) ? kk : vv;

    const int lane = threadIdx.x & 31;
    const int w    = threadIdx.x >> 5;
    const int wm = w & 1, wn = w >> 1;
    const int row0 = blockIdx.y * 128, col0 = blockIdx.x * 64;

    GemmAcc acc;
    gemm_mainloop(A, W, row0, col0, sb, acc);

    const int g = lane >> 2, tq = lane & 3;
#pragma unroll
    for (int i = 0; i < 4; i++) {
        const int m0r = row0 + wm * 64 + i * 16 + g;
#pragma unroll
        for (int j = 0; j < 4; j++) {
            const int col = col0 + wn * 32 + j * 8 + tq * 2;
            const float b0 = bias[col], b1 = bias[col + 1];
            const int h = col >> 6, d = col & 63;
#pragma unroll
            for (int half = 0; half < 2; half++) {
                const int m = m0r + half * 8;
                const int b = m >> 11, s = m & 2047;
                const float v0 = (acc.c[i][j][half * 2 + 0] + b0) * alpha;
                const float v1 = (acc.c[i][j][half * 2 + 1] + b1) * alpha;
                const size_t o = (((size_t)(b * HH + h) * SS + s) << 6) + d;
                *(__half2*)(O + o) = __floats2half2_rn(v0, v1);
            }
        }
    }
}

// ---------------------------------------------------------------------------
// Flash attention, fp16 1-pass, m32 warps, max-free softmax (log2 domain,
// S init -8). Masking post-exp2 via packed bitmask. 2 CTAs/SM; 4-stage ring.
// ---------------------------------------------------------------------------
#define DPADB    144
#define AQROWS   128
#define QTILE_B  (AQROWS * DPADB)       // 18432
#define KVT_B    (64 * DPADB)           // 9216
#define AOFF_Q   0
#define AOFF_ST  QTILE_B
#define STAGE_B  (2 * KVT_B)            // 18432
#define AOFF_KH  0
#define AOFF_VH  (1 * KVT_B)
#define SMEM_ATT (QTILE_B + 4 * STAGE_B)   // 92160

__global__ __launch_bounds__(128, 2)
void attn_mma_kernel(const __half* __restrict__ Q,
                     const __half* __restrict__ K,
                     const __half* __restrict__ V,
                     const unsigned long long* __restrict__ mbits,
                     __half* __restrict__ C)
{
    extern __shared__ char smem[];
    const uint32_t sb = smem_u32(smem);
    const int tid = threadIdx.x, lane = tid & 31, w = tid >> 5;   // w: 0..3
    const int bh = blockIdx.y, b = bh >> 4, h = bh & 15;
    const int q0 = blockIdx.x * AQROWS;
    const size_t hoff = (size_t)bh * SS * 64;

    auto issue_kv = [&](int kt) {
        const uint32_t st = sb + AOFF_ST + (uint32_t)(kt & 3) * STAGE_B;
#pragma unroll
        for (int u = tid; u < 512; u += 128) {
            const int r = u >> 3, sg = u & 7;
            const uint32_t so = (uint32_t)(r * DPADB + sg * 16);
            const size_t go = hoff + (size_t)(kt * 64 + r) * 64 + sg * 8;
            CP_ASYNC16(st + AOFF_KH + so, K + go);
            CP_ASYNC16(st + AOFF_VH + so, V + go);
        }
    };

    for (int u = tid; u < 1024; u += 128) {
        const int r = u >> 3, sg = u & 7;
        const uint32_t so = (uint32_t)(r * DPADB + sg * 16);
        const size_t go = hoff + (size_t)(q0 + r) * 64 + sg * 8;
        CP_ASYNC16(sb + AOFF_Q + so, Q + go);
    }
    issue_kv(0); CP_COMMIT();
    issue_kv(1); CP_COMMIT();
    issue_kv(2); CP_COMMIT();
    CP_WAIT(2); __syncthreads();   // Q + stage 0 ready

    // Q fragments: 2 row-blocks x 4 k-chunks
    uint32_t qf[2][4][4];
#pragma unroll
    for (int rb = 0; rb < 2; rb++) {
        const uint32_t ao = (uint32_t)((w * 32 + rb * 16 + (lane & 15)) * DPADB
                                       + ((lane >> 4) & 1) * 16);
#pragma unroll
        for (int c = 0; c < 4; c++)
            ldm_x4(qf[rb][c], sb + AOFF_Q + ao + c * 32);
    }

    const uint32_t koff = (uint32_t)(((((lane >> 4) & 1) * 8) + (lane & 7)) * DPADB
                                     + ((lane >> 3) & 1) * 16);
    const uint32_t voff = (uint32_t)((lane & 15) * DPADB + ((lane >> 4) & 1) * 16);

    float O[2][8][4];
#pragma unroll
    for (int rb = 0; rb < 2; rb++)
#pragma unroll
        for (int j = 0; j < 8; j++)
#pragma unroll
            for (int e = 0; e < 4; e++) O[rb][j][e] = 0.f;
    float l[4] = { 0.f, 0.f, 0.f, 0.f };

    const int g = lane >> 2;
    const int tq2 = (lane & 3) * 2;
    const unsigned long long* bp =
        mbits + ((size_t)(b * SS) + q0 + w * 32 + g) * 32;

    for (int kt = 0; kt < 32; kt++) {
        CP_WAIT(1);
        __syncthreads();

        // mask bits (latency hidden by QK MMAs below)
        unsigned long long B0 = bp[kt];
        unsigned long long B1 = bp[kt + 256];
        unsigned long long B2 = bp[kt + 512];
        unsigned long long B3 = bp[kt + 768];

        // ---- QK: S = Q.K - 8 (log2 domain, static shift via C-init)
        const uint32_t st = sb + AOFF_ST + (uint32_t)(kt & 3) * STAGE_B;
        float S[2][8][4];
#pragma unroll
        for (int rb = 0; rb < 2; rb++)
#pragma unroll
            for (int j = 0; j < 8; j++)
#pragma unroll
                for (int e = 0; e < 4; e++) S[rb][j][e] = -8.f;
#pragma unroll
        for (int c = 0; c < 4; c++)
#pragma unroll
            for (int jp = 0; jp < 4; jp++) {
                uint32_t tk[4];
                const uint32_t ko = (uint32_t)(jp * 16 * DPADB) + koff + c * 32;
                ldm_x4(tk, st + AOFF_KH + ko);
                mma16816(S[0][jp*2],   qf[0][c], tk);
                mma16816(S[0][jp*2+1], qf[0][c], tk + 2);
                mma16816(S[1][jp*2],   qf[1][c], tk);
                mma16816(S[1][jp*2+1], qf[1][c], tk + 2);
            }

        // ---- exp2 (no max pass) + bitmask zeroing + pack P
        uint32_t PH[2][8][2];
#pragma unroll
        for (int j = 0; j < 8; j++) {
            const int sh = j * 8 + tq2;
            const uint32_t b0 = (uint32_t)(B0 >> sh);
            const uint32_t b1 = (uint32_t)(B1 >> sh);
            const uint32_t b2 = (uint32_t)(B2 >> sh);
            const uint32_t b3 = (uint32_t)(B3 >> sh);
            float p00 = exp2f(S[0][j][0]);
            float p01 = exp2f(S[0][j][1]);
            float p02 = exp2f(S[0][j][2]);
            float p03 = exp2f(S[0][j][3]);
            float p10 = exp2f(S[1][j][0]);
            float p11 = exp2f(S[1][j][1]);
            float p12 = exp2f(S[1][j][2]);
            float p13 = exp2f(S[1][j][3]);
            p00 = (b0 & 1u) ? 0.f : p00;  p01 = (b0 & 2u) ? 0.f : p01;
            p02 = (b1 & 1u) ? 0.f : p02;  p03 = (b1 & 2u) ? 0.f : p03;
            p10 = (b2 & 1u) ? 0.f : p10;  p11 = (b2 & 2u) ? 0.f : p11;
            p12 = (b3 & 1u) ? 0.f : p12;  p13 = (b3 & 2u) ? 0.f : p13;
            l[0] += p00 + p01; l[1] += p02 + p03;
            l[2] += p10 + p11; l[3] += p12 + p13;
            PH[0][j][0] = bc32(__floats2half2_rn(p00, p01));
            PH[0][j][1] = bc32(__floats2half2_rn(p02, p03));
            PH[1][j][0] = bc32(__floats2half2_rn(p10, p11));
            PH[1][j][1] = bc32(__floats2half2_rn(p12, p13));
        }

        // ---- PV: O += P . V; V frags shared across row-blocks
#pragma unroll
        for (int t = 0; t < 4; t++) {
            uint32_t a0[4] = { PH[0][2*t][0], PH[0][2*t][1],
                               PH[0][2*t+1][0], PH[0][2*t+1][1] };
            uint32_t a1[4] = { PH[1][2*t][0], PH[1][2*t][1],
                               PH[1][2*t+1][0], PH[1][2*t+1][1] };
#pragma unroll
            for (int jp = 0; jp < 4; jp++) {
                uint32_t tv[4];
                const uint32_t vo = (uint32_t)(t * 16 * DPADB) + voff + jp * 32;
                ldm_x4t(tv, st + AOFF_VH + vo);
                mma16816(O[0][jp*2],   a0, tv);
                mma16816(O[0][jp*2+1], a0, tv + 2);
                mma16816(O[1][jp*2],   a1, tv);
                mma16816(O[1][jp*2+1], a1, tv + 2);
            }
        }

        if (kt + 3 < 32) issue_kv(kt + 3);
        CP_COMMIT();
    }

    // ---- epilogue: 4 rows per thread, single l reduce
#pragma unroll
    for (int rr = 0; rr < 4; rr++) {
        l[rr] += __shfl_xor_sync(0xFFFFFFFFu, l[rr], 1);
        l[rr] += __shfl_xor_sync(0xFFFFFFFFu, l[rr], 2);
    }
    const int colb = h * 64 + tq2;
#pragma unroll
    for (int rr = 0; rr < 4; rr++) {
        const int rb = rr >> 1, hh = rr & 1;
        const float inv = 1.f / l[rr];
        const size_t r = (size_t)(b * SS) + q0 + w * 32 + g + rr * 8;
#pragma unroll
        for (int j = 0; j < 8; j++) {
            *(__half2*)(C + r * DD + colb + j * 8) =
                __floats2half2_rn(O[rb][j][hh*2] * inv, O[rb][j][hh*2+1] * inv);
        }
    }
}

// ---------------------------------------------------------------------------
// Launch
// ---------------------------------------------------------------------------
extern "C" void kernel_launch(void* const* d_in, const int* in_sizes, int n_in,
                              void* d_out, int out_size)
{
    const float* query = (const float*)d_in[0];
    const int*   mask  = (const int*)d_in[1];
    const float* Wq = (const float*)d_in[2];
    const float* bq = (const float*)d_in[3];
    const float* Wk = (const float*)d_in[4];
    const float* bk = (const float*)d_in[5];
    const float* Wv = (const float*)d_in[6];
    const float* bv = (const float*)d_in[7];
    const float* Wo = (const float*)d_in[8];
    const float* bo = (const float*)d_in[9];
    float* out = (float*)d_out;

    __half *xx, *wp, *qq, *kk, *vv, *cc;
    unsigned int* mb;
    cudaGetSymbolAddress((void**)&xx, g_x);
    cudaGetSymbolAddress((void**)&wp, g_w);
    cudaGetSymbolAddress((void**)&qq, g_q);
    cudaGetSymbolAddress((void**)&kk, g_k);
    cudaGetSymbolAddress((void**)&vv, g_v);
    cudaGetSymbolAddress((void**)&cc, g_c);
    cudaGetSymbolAddress((void**)&mb, g_mbits);

    cudaFuncSetAttribute(gemm_qkv_kernel,
                         cudaFuncAttributeMaxDynamicSharedMemorySize, SMEM_GG);
    cudaFuncSetAttribute(gemm_out_kernel,
                         cudaFuncAttributeMaxDynamicSharedMemorySize, SMEM_GG);
    cudaFuncSetAttribute(attn_mma_kernel,
                         cudaFuncAttributeMaxDynamicSharedMemorySize, SMEM_ATT);

    prep_kernel<<<PREP_TOT / 256, 256>>>(Wq, Wk, Wv, Wo, query, mask,
                                         wp, xx, mb);

    dim3 qkvG(DD / 64, MTOT / 128, 3);      // (16, 32, 3) = 1536 CTAs
    gemm_qkv_kernel<<<qkvG, 128, SMEM_GG>>>(xx, wp, bq, bk, bv, qq, kk, vv);

    dim3 aG(SS / AQROWS, BB * HH);          // (16, 32) = 512 CTAs
    attn_mma_kernel<<<aG, 128, SMEM_ATT>>>(
        qq, kk, vv, (const unsigned long long*)mb, cc);

    dim3 oG(DD / 64, MTOT / 128);           // (16, 32)
    gemm_out_kernel<<<oG, 128, SMEM_GG>>>(cc, wp + 3 * (size_t)DD * DD, bo, out);
}